// round 15
// baseline (speedup 1.0000x reference)
#include <cuda_runtime.h>
#include <cuda_fp16.h>
#include <math.h>

#define NN   100000
#define NE   800000
#define FIN  128
#define C    32
#define D    16
#define CST  1e-5f

// ---------- persistent scratch (device globals; no allocation allowed) ----------
__device__ float  g_Q[NN * C];                         // 12.8 MB
__device__ __align__(16) __half g_KV0[NN * 64];        // 12.8 MB: 32 K + 16 V + 16 pad (128B row)
__device__ __align__(16) __half g_Kh[2][NN * C];       // 2 x 6.4 MB  (K1, K2)
// M rows stored TRANSPOSED: element idx = j*32 + i  (j in [0,16), i in [0,32))
// -> 64-lane node-group: lane u owns elements [8u, 8u+8) = 1 uint4
__device__ __align__(16) __half g_Mh[2][NN * C * D];   // 2 x 102.4 MB (row = 512 halfs = 64 uint4)
__device__ __align__(16) int g_deg[NN];
__device__ int    g_off[NN + 1];
__device__ int    g_cur[NN];
__device__ int    g_adj[NE];

// ---------------------------------------------- inline edge dtype detection ---
__device__ __forceinline__ int edge_is64(const void* __restrict__ ei, int n) {
    const long long* p = (const long long*)ei;
    long long v = p[threadIdx.x & 15];
    return __all_sync(0xffffffffu, v >= 0 && v < (long long)n);
}

// -------------------------------------------------------------- half helpers --
__device__ __forceinline__ void cvt8(uint4 u, float* f) {
    float2 p;
    p = __half22float2(*reinterpret_cast<const __half2*>(&u.x)); f[0] = p.x; f[1] = p.y;
    p = __half22float2(*reinterpret_cast<const __half2*>(&u.y)); f[2] = p.x; f[3] = p.y;
    p = __half22float2(*reinterpret_cast<const __half2*>(&u.z)); f[4] = p.x; f[5] = p.y;
    p = __half22float2(*reinterpret_cast<const __half2*>(&u.w)); f[6] = p.x; f[7] = p.y;
}
__device__ __forceinline__ uint4 pack8(const float* f) {
    __half2 h0 = __floats2half2_rn(f[0], f[1]);
    __half2 h1 = __floats2half2_rn(f[2], f[3]);
    __half2 h2 = __floats2half2_rn(f[4], f[5]);
    __half2 h3 = __floats2half2_rn(f[6], f[7]);
    uint4 u;
    u.x = *(unsigned*)&h0; u.y = *(unsigned*)&h1;
    u.z = *(unsigned*)&h2; u.w = *(unsigned*)&h3;
    return u;
}
__device__ __forceinline__ void loadQ8(const float* __restrict__ q, float* qv) {
    const float4* qp = (const float4*)q;
    float4 a = qp[0], b = qp[1];
    qv[0]=a.x; qv[1]=a.y; qv[2]=a.z; qv[3]=a.w;
    qv[4]=b.x; qv[5]=b.y; qv[6]=b.z; qv[7]=b.w;
}

// ----------------------------------------- front-end + edge count (fused) -----
__global__ void featcount_kernel(const float* __restrict__ feat,
                                 const void*  __restrict__ ei, int ne,
                                 const float* __restrict__ Win, const float* __restrict__ bin,
                                 const float* __restrict__ Wq,  const float* __restrict__ bq,
                                 const float* __restrict__ Wk,  const float* __restrict__ bk,
                                 const float* __restrict__ Wv,  const float* __restrict__ bv,
                                 const float* __restrict__ hopwise,
                                 float* __restrict__ out, int n) {
    int gtid = blockIdx.x * 256 + threadIdx.x;
    int is64 = edge_is64(ei, n);
    if (gtid < ne) {
        int c = is64 ? (int)((const long long*)ei)[ne + gtid]
                     : ((const int*)ei)[ne + gtid];
        atomicAdd(&g_deg[c], 1);
    }

    __shared__ float sWin[FIN * C];
    __shared__ float sWq[C * C], sWk[C * C], sWv[C * D];
    __shared__ float sb[3 * C + D];
    __shared__ float sx [8][FIN];
    __shared__ float sxs[8][C];

    int tid = threadIdx.x;
    for (int i = tid; i < FIN * C; i += 256) sWin[i] = Win[i];
    for (int i = tid; i < C * C;   i += 256) { sWq[i] = Wq[i]; sWk[i] = Wk[i]; }
    for (int i = tid; i < C * D;   i += 256) sWv[i] = Wv[i];
    if (tid < C) { sb[tid] = bin[tid]; sb[C + tid] = bq[tid]; sb[2 * C + tid] = bk[tid]; }
    if (tid < D) sb[3 * C + tid] = bv[tid];
    __syncthreads();

    int w = tid >> 5, lane = tid & 31;
    int node = blockIdx.x * 8 + w;
    if (node >= n) return;

    ((float4*)sx[w])[lane] = ((const float4*)feat)[node * (FIN / 4) + lane];
    __syncwarp();

    float acc = sb[lane];
#pragma unroll 8
    for (int i = 0; i < FIN; i++) acc = fmaf(sx[w][i], sWin[i * C + lane], acc);
    float x = fmaxf(acc, 0.f);
    sxs[w][lane] = x;
    __syncwarp();

    float qz = sb[C + lane], kz = sb[2 * C + lane];
    float vz = (lane < D) ? sb[3 * C + lane] : 0.f;
#pragma unroll
    for (int i = 0; i < C; i++) {
        float xi = sxs[w][i];
        qz = fmaf(xi, sWq[i * C + lane], qz);
        kz = fmaf(xi, sWk[i * C + lane], kz);
        if (lane < D) vz = fmaf(xi, sWv[i * D + lane], vz);
    }
    float q = (qz > 0.f) ? 1.f + qz : expf(qz);  // 1 + elu
    float k = (kz > 0.f) ? 1.f + kz : expf(kz);

    g_Q[node * C + lane] = q;

    __half* kv = &g_KV0[(size_t)node * 64];
    kv[lane] = __float2half_rn(k);
    if (lane < D) kv[32 + lane] = __float2half_rn(vz);
    if (lane < 16) kv[48 + lane] = __half(0.f);

    if (lane < D) out[node * D + lane] = hopwise[0] * vz;
}

// --------------------------- single-block tiled exclusive scan (int4-wide) ----
__global__ void scan1_kernel(int n) {
    __shared__ int wsum[32];
    __shared__ int carry;
    int tid = threadIdx.x, lane = tid & 31, w = tid >> 5;
    if (tid == 0) carry = 0;
    __syncthreads();
    for (int base = 0; base < n; base += 4096) {
        int i = base + tid * 4;
        int4 v = make_int4(0, 0, 0, 0);
        if (i + 3 < n) v = *(const int4*)&g_deg[i];
        else {
            if (i     < n) v.x = g_deg[i];
            if (i + 1 < n) v.y = g_deg[i + 1];
            if (i + 2 < n) v.z = g_deg[i + 2];
        }
        int tsum = v.x + v.y + v.z + v.w;
        int s = tsum;
#pragma unroll
        for (int o = 1; o < 32; o <<= 1) {
            int t = __shfl_up_sync(0xffffffffu, s, o);
            if (lane >= o) s += t;
        }
        if (lane == 31) wsum[w] = s;
        __syncthreads();
        if (w == 0) {
            int ws = wsum[lane];
#pragma unroll
            for (int o = 1; o < 32; o <<= 1) {
                int t = __shfl_up_sync(0xffffffffu, ws, o);
                if (lane >= o) ws += t;
            }
            wsum[lane] = ws;
        }
        __syncthreads();
        int pre   = (w ? wsum[w - 1] : 0);
        int total = wsum[31];
        int o0 = carry + pre + s - tsum;
        int o1 = o0 + v.x, o2 = o1 + v.y, o3 = o2 + v.z;
        if (i     < n) { g_off[i]     = o0; g_cur[i]     = o0; }
        if (i + 1 < n) { g_off[i + 1] = o1; g_cur[i + 1] = o1; }
        if (i + 2 < n) { g_off[i + 2] = o2; g_cur[i + 2] = o2; }
        if (i + 3 < n) { g_off[i + 3] = o3; g_cur[i + 3] = o3; }
        __syncthreads();
        if (tid == 0) carry += total;
        __syncthreads();
    }
    if (tid == 0) g_off[n] = carry;
}

__global__ void scatter_kernel(const void* __restrict__ ei, int ne, int n) {
    const long long* p64 = (const long long*)ei;
    const int*       p32 = (const int*)ei;
    int is64 = edge_is64(ei, n);
    for (int e = blockIdx.x * blockDim.x + threadIdx.x; e < ne; e += gridDim.x * blockDim.x) {
        int c = is64 ? (int)p64[ne + e] : p32[ne + e];
        int r = is64 ? (int)p64[e]      : p32[e];
        int p = atomicAdd(&g_cur[c], 1);
        g_adj[p] = r;
    }
}

// ------------------------------------------------------------- hop 1 (rank-1) -
// 64 lanes per node (2 warps). Lane u: j = u>>2, q = u&3; owns M1[j][8q..8q+8)
// (= transposed elements [8u,8u+8) = uint4 index u) and K-slice [8q,8q+8).
__global__ void hop1_kernel(float* __restrict__ out,
                            const float* __restrict__ hopwise, int n) {
    int t = threadIdx.x;
    int c = blockIdx.x * 4 + (t >> 6);
    if (c >= n) return;
    int u = t & 63, lane = t & 31;
    int j = u >> 2, q = u & 3;
    int start = g_off[c], end = g_off[c + 1];

    float macc[8], kacc[8];
#pragma unroll
    for (int m = 0; m < 8; m++) { macc[m] = 0.f; kacc[m] = 0.f; }

    for (int base = start; base < end; base += 32) {
        int cnt = end - base; if (cnt > 32) cnt = 32;
        int myadj = (lane < cnt) ? g_adj[base + lane] : 0;
#pragma unroll 4
        for (int e = 0; e < cnt; e++) {
            int r = __shfl_sync(0xffffffffu, myadj, e);
            const __half* kv = &g_KV0[(size_t)r * 64];
            uint4 ua = ((const uint4*)kv)[q];            // K halfs [8q, 8q+8)
            float v = __half2float(kv[32 + j]);
            float kf[8];
            cvt8(ua, kf);
#pragma unroll
            for (int m = 0; m < 8; m++) {
                kacc[m] += kf[m];
                macc[m] = fmaf(kf[m], v, macc[m]);
            }
        }
    }

    // store M1 (uint4 index u) and K1 (lanes j==0 hold the 4 K-slices)
    ((uint4*)&g_Mh[0][(size_t)c * 512])[u] = pack8(macc);
    if (u < 4) ((uint4*)&g_Kh[0][c * 32])[u] = pack8(kacc);

    // epilogue: H_j = sum_i Q_i M[j][i], C = sum_i Q_i K1_i (quad reduce)
    float qv[8];
    loadQ8(&g_Q[c * 32 + 8 * q], qv);
    float hp = 0.f, cp = 0.f;
#pragma unroll
    for (int m = 0; m < 8; m++) {
        hp = fmaf(qv[m], macc[m], hp);
        cp = fmaf(qv[m], kacc[m], cp);
    }
    hp += __shfl_xor_sync(0xffffffffu, hp, 1);
    hp += __shfl_xor_sync(0xffffffffu, hp, 2);
    cp += __shfl_xor_sync(0xffffffffu, cp, 1);
    cp += __shfl_xor_sync(0xffffffffu, cp, 2);
    if (q == 0) out[c * 16 + j] += hopwise[1] * hp / (cp + CST);
}

// ------------------------------------------------------------- hops 2 & 3 -----
// 64 lanes per node; lane u gathers uint4 [8u,8u+8) of the transposed M row
// + one K half (i = lane). No smem, no syncthreads.
__global__ void hop_kernel(float* __restrict__ out,
                           const float* __restrict__ hopwise,
                           int hop, int src, int writeM, int n) {
    int t = threadIdx.x;
    int c = blockIdx.x * 4 + (t >> 6);
    if (c >= n) return;
    int u = t & 63, lane = t & 31;
    int j = u >> 2, q = u & 3;
    int start = g_off[c], end = g_off[c + 1];

    const uint4*  __restrict__ Mold = (const uint4*)g_Mh[src];
    const __half* __restrict__ Kold = g_Kh[src];

    float macc[8];
#pragma unroll
    for (int m = 0; m < 8; m++) macc[m] = 0.f;
    float kacc = 0.f;   // K[i = lane]

    for (int base = start; base < end; base += 32) {
        int cnt = end - base; if (cnt > 32) cnt = 32;
        int myadj = (lane < cnt) ? g_adj[base + lane] : 0;
#pragma unroll 4
        for (int e = 0; e < cnt; e++) {
            int r = __shfl_sync(0xffffffffu, myadj, e);
            uint4 ua = Mold[(size_t)r * 64 + u];
            float f[8];
            cvt8(ua, f);
#pragma unroll
            for (int m = 0; m < 8; m++) macc[m] += f[m];
            kacc += __half2float(Kold[r * 32 + lane]);
        }
    }

    if (writeM) {
        ((uint4*)&g_Mh[src ^ 1][(size_t)c * 512])[u] = pack8(macc);
        if (u < 32) {   // warp 0 of the group writes K
            float kn = __shfl_down_sync(0xffffffffu, kacc, 1);
            if (!(lane & 1)) {
                __half2 kk = __floats2half2_rn(kacc, kn);
                *(unsigned*)&g_Kh[src ^ 1][c * 32 + lane] = *(unsigned*)&kk;
            }
        }
    }

    // epilogue
    float qv[8];
    loadQ8(&g_Q[c * 32 + 8 * q], qv);
    float hp = 0.f;
#pragma unroll
    for (int m = 0; m < 8; m++) hp = fmaf(qv[m], macc[m], hp);
    hp += __shfl_xor_sync(0xffffffffu, hp, 1);
    hp += __shfl_xor_sync(0xffffffffu, hp, 2);

    float cp = g_Q[c * 32 + lane] * kacc;
#pragma unroll
    for (int off = 16; off >= 1; off >>= 1)
        cp += __shfl_xor_sync(0xffffffffu, cp, off);

    if (q == 0) out[c * 16 + j] += hopwise[hop + 1] * hp / (cp + CST);
}

// ------------------------------------------------------------------ launch ----
extern "C" void kernel_launch(void* const* d_in, const int* in_sizes, int n_in,
                              void* d_out, int out_size) {
    const float* feat    = (const float*)d_in[0];
    const void*  ei      = d_in[1];
    const float* Win     = (const float*)d_in[2];
    const float* bin     = (const float*)d_in[3];
    const float* Wq      = (const float*)d_in[4];
    const float* bq      = (const float*)d_in[5];
    const float* Wk      = (const float*)d_in[6];
    const float* bk      = (const float*)d_in[7];
    const float* Wv      = (const float*)d_in[8];
    const float* bv      = (const float*)d_in[9];
    const float* hopwise = (const float*)d_in[10];
    float*       out     = (float*)d_out;

    int n  = in_sizes[0] / FIN;   // 100000
    int ne = in_sizes[1] / 2;     // 800000
    int nb8 = (n + 7) / 8;
    int nb4 = (n + 3) / 4;

    void* degp = nullptr;
    cudaGetSymbolAddress(&degp, g_deg);
    cudaMemsetAsync(degp, 0, NN * sizeof(int));

    featcount_kernel<<<nb8, 256>>>(feat, ei, ne, Win, bin, Wq, bq,
                                   Wk, bk, Wv, bv, hopwise, out, n);
    scan1_kernel<<<1, 1024>>>(n);
    scatter_kernel<<<1024, 256>>>(ei, ne, n);

    hop1_kernel<<<nb4, 256>>>(out, hopwise, n);
    hop_kernel<<<nb4, 256>>>(out, hopwise, 1, 0, 1, n);
    hop_kernel<<<nb4, 256>>>(out, hopwise, 2, 1, 0, n);
}

// round 16
// speedup vs baseline: 1.0837x; 1.0837x over previous
#include <cuda_runtime.h>
#include <cuda_fp16.h>
#include <math.h>

#define NN   100000
#define NE   800000
#define FIN  128
#define C    32
#define D    16
#define CST  1e-5f

// ---------- persistent scratch (device globals; no allocation allowed) ----------
__device__ float  g_Q[NN * C];                         // 12.8 MB
__device__ __align__(16) __half g_KV0[NN * 64];        // 12.8 MB: 32 K + 16 V + 16 pad (128B row)
__device__ __align__(16) __half g_Kh[2][NN * C];       // 2 x 6.4 MB  (K1, K2)
// M rows stored TRANSPOSED: element idx = j*32 + i  (j in [0,16), i in [0,32))
// -> warp lane l owns elements [16l, 16l+16) = 2 contiguous uint4
__device__ __align__(16) __half g_Mh[2][NN * C * D];   // 2 x 102.4 MB (row = 512 halfs)
__device__ __align__(16) int g_deg[NN];
__device__ int    g_off[NN + 1];
__device__ int    g_cur[NN];
__device__ int    g_adj[NE];

// ---------------------------------------------- inline edge dtype detection ---
__device__ __forceinline__ int edge_is64(const void* __restrict__ ei, int n) {
    const long long* p = (const long long*)ei;
    long long v = p[threadIdx.x & 15];
    return __all_sync(0xffffffffu, v >= 0 && v < (long long)n);
}

// -------------------------------------------------------------- half helpers --
__device__ __forceinline__ void cvt8(uint4 u, float* f) {
    float2 p;
    p = __half22float2(*reinterpret_cast<const __half2*>(&u.x)); f[0] = p.x; f[1] = p.y;
    p = __half22float2(*reinterpret_cast<const __half2*>(&u.y)); f[2] = p.x; f[3] = p.y;
    p = __half22float2(*reinterpret_cast<const __half2*>(&u.z)); f[4] = p.x; f[5] = p.y;
    p = __half22float2(*reinterpret_cast<const __half2*>(&u.w)); f[6] = p.x; f[7] = p.y;
}
__device__ __forceinline__ uint4 pack8(const float* f) {
    __half2 h0 = __floats2half2_rn(f[0], f[1]);
    __half2 h1 = __floats2half2_rn(f[2], f[3]);
    __half2 h2 = __floats2half2_rn(f[4], f[5]);
    __half2 h3 = __floats2half2_rn(f[6], f[7]);
    uint4 u;
    u.x = *(unsigned*)&h0; u.y = *(unsigned*)&h1;
    u.z = *(unsigned*)&h2; u.w = *(unsigned*)&h3;
    return u;
}

// ---------------------------------------------------------------- CSR chain ---
__global__ void count_kernel(const void* __restrict__ ei, int ne, int n) {
    int is64 = edge_is64(ei, n);
    const long long* p64 = (const long long*)ei;
    const int*       p32 = (const int*)ei;
    for (int e = blockIdx.x * blockDim.x + threadIdx.x; e < ne; e += gridDim.x * blockDim.x) {
        int c = is64 ? (int)p64[ne + e] : p32[ne + e];
        atomicAdd(&g_deg[c], 1);
    }
}

__global__ void scan1_kernel(int n) {
    __shared__ int wsum[32];
    __shared__ int carry;
    int tid = threadIdx.x, lane = tid & 31, w = tid >> 5;
    if (tid == 0) carry = 0;
    __syncthreads();
    for (int base = 0; base < n; base += 4096) {
        int i = base + tid * 4;
        int4 v = make_int4(0, 0, 0, 0);
        if (i + 3 < n) v = *(const int4*)&g_deg[i];
        else {
            if (i     < n) v.x = g_deg[i];
            if (i + 1 < n) v.y = g_deg[i + 1];
            if (i + 2 < n) v.z = g_deg[i + 2];
        }
        int tsum = v.x + v.y + v.z + v.w;
        int s = tsum;
#pragma unroll
        for (int o = 1; o < 32; o <<= 1) {
            int t = __shfl_up_sync(0xffffffffu, s, o);
            if (lane >= o) s += t;
        }
        if (lane == 31) wsum[w] = s;
        __syncthreads();
        if (w == 0) {
            int ws = wsum[lane];
#pragma unroll
            for (int o = 1; o < 32; o <<= 1) {
                int t = __shfl_up_sync(0xffffffffu, ws, o);
                if (lane >= o) ws += t;
            }
            wsum[lane] = ws;
        }
        __syncthreads();
        int pre   = (w ? wsum[w - 1] : 0);
        int total = wsum[31];
        int o0 = carry + pre + s - tsum;
        int o1 = o0 + v.x, o2 = o1 + v.y, o3 = o2 + v.z;
        if (i     < n) { g_off[i]     = o0; g_cur[i]     = o0; }
        if (i + 1 < n) { g_off[i + 1] = o1; g_cur[i + 1] = o1; }
        if (i + 2 < n) { g_off[i + 2] = o2; g_cur[i + 2] = o2; }
        if (i + 3 < n) { g_off[i + 3] = o3; g_cur[i + 3] = o3; }
        __syncthreads();
        if (tid == 0) carry += total;
        __syncthreads();
    }
    if (tid == 0) g_off[n] = carry;
}

__global__ void scatter_kernel(const void* __restrict__ ei, int ne, int n) {
    const long long* p64 = (const long long*)ei;
    const int*       p32 = (const int*)ei;
    int is64 = edge_is64(ei, n);
    for (int e = blockIdx.x * blockDim.x + threadIdx.x; e < ne; e += gridDim.x * blockDim.x) {
        int c = is64 ? (int)p64[ne + e] : p32[ne + e];
        int r = is64 ? (int)p64[e]      : p32[e];
        int p = atomicAdd(&g_cur[c], 1);
        g_adj[p] = r;
    }
}

// ---------------------------------------------------------- front-end (feat) --
__global__ void feat_kernel(const float* __restrict__ feat,
                            const float* __restrict__ Win, const float* __restrict__ bin,
                            const float* __restrict__ Wq,  const float* __restrict__ bq,
                            const float* __restrict__ Wk,  const float* __restrict__ bk,
                            const float* __restrict__ Wv,  const float* __restrict__ bv,
                            const float* __restrict__ hopwise,
                            float* __restrict__ out, int n) {
    __shared__ float sWin[FIN * C];
    __shared__ float sWq[C * C], sWk[C * C], sWv[C * D];
    __shared__ float sb[3 * C + D];
    __shared__ float sx [8][FIN];
    __shared__ float sxs[8][C];

    int tid = threadIdx.x;
    for (int i = tid; i < FIN * C; i += 256) sWin[i] = Win[i];
    for (int i = tid; i < C * C;   i += 256) { sWq[i] = Wq[i]; sWk[i] = Wk[i]; }
    for (int i = tid; i < C * D;   i += 256) sWv[i] = Wv[i];
    if (tid < C) { sb[tid] = bin[tid]; sb[C + tid] = bq[tid]; sb[2 * C + tid] = bk[tid]; }
    if (tid < D) sb[3 * C + tid] = bv[tid];
    __syncthreads();

    int w = tid >> 5, lane = tid & 31;
    int node = blockIdx.x * 8 + w;
    if (node >= n) return;

    ((float4*)sx[w])[lane] = ((const float4*)feat)[node * (FIN / 4) + lane];
    __syncwarp();

    float acc = sb[lane];
#pragma unroll 8
    for (int i = 0; i < FIN; i++) acc = fmaf(sx[w][i], sWin[i * C + lane], acc);
    float x = fmaxf(acc, 0.f);
    sxs[w][lane] = x;
    __syncwarp();

    float qz = sb[C + lane], kz = sb[2 * C + lane];
    float vz = (lane < D) ? sb[3 * C + lane] : 0.f;
#pragma unroll
    for (int i = 0; i < C; i++) {
        float xi = sxs[w][i];
        qz = fmaf(xi, sWq[i * C + lane], qz);
        kz = fmaf(xi, sWk[i * C + lane], kz);
        if (lane < D) vz = fmaf(xi, sWv[i * D + lane], vz);
    }
    float q = (qz > 0.f) ? 1.f + qz : expf(qz);  // 1 + elu
    float k = (kz > 0.f) ? 1.f + kz : expf(kz);

    g_Q[node * C + lane] = q;

    __half* kv = &g_KV0[(size_t)node * 64];
    kv[lane] = __float2half_rn(k);
    if (lane < D) kv[32 + lane] = __float2half_rn(vz);
    if (lane < 16) kv[48 + lane] = __half(0.f);

    if (lane < D) out[node * D + lane] = hopwise[0] * vz;
}

// ------------------------------------------------------------- hop 1 (rank-1) -
// Warp per node (R10 layout). Lane l: h = l&1 (i-half), j = l>>1 (V column).
__global__ void hop1_kernel(float* __restrict__ out,
                            const float* __restrict__ hopwise, int n) {
    int wid = threadIdx.x >> 5, lane = threadIdx.x & 31;
    int c = blockIdx.x * 8 + wid;
    if (c >= n) return;
    int h = lane & 1, j = lane >> 1;
    int start = g_off[c], end = g_off[c + 1];

    float macc[16], kacc[16];
#pragma unroll
    for (int m = 0; m < 16; m++) { macc[m] = 0.f; kacc[m] = 0.f; }

    for (int base = start; base < end; base += 32) {
        int cnt = end - base; if (cnt > 32) cnt = 32;
        int myadj = (lane < cnt) ? g_adj[base + lane] : 0;
#pragma unroll 4
        for (int e = 0; e < cnt; e++) {
            int r = __shfl_sync(0xffffffffu, myadj, e);
            const __half* kv = &g_KV0[(size_t)r * 64];
            const uint4* kv4 = (const uint4*)kv;
            uint4 ua = kv4[2 * h], ub = kv4[2 * h + 1];   // K halfs [16h,16h+16)
            float v = __half2float(kv[32 + j]);
            float kf[16];
            cvt8(ua, kf); cvt8(ub, kf + 8);
#pragma unroll
            for (int m = 0; m < 16; m++) {
                kacc[m] += kf[m];
                macc[m] = fmaf(kf[m], v, macc[m]);
            }
        }
    }

    // store M1 row (transposed layout: lane's 16 elements at 16*lane)
    {
        uint4* mr = (uint4*)&g_Mh[0][(size_t)c * 512];
        mr[2 * lane]     = pack8(macc);
        mr[2 * lane + 1] = pack8(macc + 8);
    }
    if (lane < 2) {
        uint4* kr = (uint4*)&g_Kh[0][c * 32];
        kr[2 * lane]     = pack8(kacc);
        kr[2 * lane + 1] = pack8(kacc + 8);
    }

    // epilogue: H_j = sum_i Q_i M[j][i],  C = sum_i Q_i K1_i
    float qv[16];
    {
        const float4* qp = (const float4*)&g_Q[c * 32 + 16 * h];
        float4 q0 = qp[0], q1 = qp[1], q2 = qp[2], q3 = qp[3];
        qv[0]=q0.x; qv[1]=q0.y; qv[2]=q0.z; qv[3]=q0.w;
        qv[4]=q1.x; qv[5]=q1.y; qv[6]=q1.z; qv[7]=q1.w;
        qv[8]=q2.x; qv[9]=q2.y; qv[10]=q2.z; qv[11]=q2.w;
        qv[12]=q3.x; qv[13]=q3.y; qv[14]=q3.z; qv[15]=q3.w;
    }
    float hp = 0.f, cp = 0.f;
#pragma unroll
    for (int m = 0; m < 16; m++) {
        hp = fmaf(qv[m], macc[m], hp);
        cp = fmaf(qv[m], kacc[m], cp);
    }
    float Hj = hp + __shfl_xor_sync(0xffffffffu, hp, 1);
    float Cv = cp + __shfl_xor_sync(0xffffffffu, cp, 1);
    if (h == 0) out[c * 16 + j] += hopwise[1] * Hj / (Cv + CST);
}

// ------------------------------------------------------------- hops 2 & 3 -----
// Warp per node (R10 layout); lane l gathers 2 uint4 + one K half.
__global__ void hop_kernel(float* __restrict__ out,
                           const float* __restrict__ hopwise,
                           int hop, int src, int writeM, int n) {
    int wid = threadIdx.x >> 5, lane = threadIdx.x & 31;
    int c = blockIdx.x * 8 + wid;
    if (c >= n) return;
    int h = lane & 1, j = lane >> 1;
    int start = g_off[c], end = g_off[c + 1];

    const uint4*  __restrict__ Mold = (const uint4*)g_Mh[src];
    const __half* __restrict__ Kold = g_Kh[src];

    float macc[16];
#pragma unroll
    for (int m = 0; m < 16; m++) macc[m] = 0.f;
    float kacc = 0.f;   // K[i = lane]

    for (int base = start; base < end; base += 32) {
        int cnt = end - base; if (cnt > 32) cnt = 32;
        int myadj = (lane < cnt) ? g_adj[base + lane] : 0;
#pragma unroll 4
        for (int e = 0; e < cnt; e++) {
            int r = __shfl_sync(0xffffffffu, myadj, e);
            uint4 ua = Mold[(size_t)r * 64 + 2 * lane];
            uint4 ub = Mold[(size_t)r * 64 + 2 * lane + 1];
            float f[16];
            cvt8(ua, f); cvt8(ub, f + 8);
#pragma unroll
            for (int m = 0; m < 16; m++) macc[m] += f[m];
            kacc += __half2float(Kold[r * 32 + lane]);
        }
    }

    if (writeM) {
        uint4* mr = (uint4*)&g_Mh[src ^ 1][(size_t)c * 512];
        mr[2 * lane]     = pack8(macc);
        mr[2 * lane + 1] = pack8(macc + 8);
        float kn = __shfl_down_sync(0xffffffffu, kacc, 1);
        if (!(lane & 1)) {
            __half2 kk = __floats2half2_rn(kacc, kn);
            *(unsigned*)&g_Kh[src ^ 1][c * 32 + lane] = *(unsigned*)&kk;
        }
    }

    // epilogue
    float qv[16];
    {
        const float4* qp = (const float4*)&g_Q[c * 32 + 16 * h];
        float4 q0 = qp[0], q1 = qp[1], q2 = qp[2], q3 = qp[3];
        qv[0]=q0.x; qv[1]=q0.y; qv[2]=q0.z; qv[3]=q0.w;
        qv[4]=q1.x; qv[5]=q1.y; qv[6]=q1.z; qv[7]=q1.w;
        qv[8]=q2.x; qv[9]=q2.y; qv[10]=q2.z; qv[11]=q2.w;
        qv[12]=q3.x; qv[13]=q3.y; qv[14]=q3.z; qv[15]=q3.w;
    }
    float hp = 0.f;
#pragma unroll
    for (int m = 0; m < 16; m++) hp = fmaf(qv[m], macc[m], hp);
    float Hj = hp + __shfl_xor_sync(0xffffffffu, hp, 1);

    float cp = g_Q[c * 32 + lane] * kacc;
#pragma unroll
    for (int off = 16; off >= 1; off >>= 1)
        cp += __shfl_xor_sync(0xffffffffu, cp, off);

    if (h == 0) out[c * 16 + j] += hopwise[hop + 1] * Hj / (cp + CST);
}

// ------------------------------------------------------------------ launch ----
extern "C" void kernel_launch(void* const* d_in, const int* in_sizes, int n_in,
                              void* d_out, int out_size) {
    const float* feat    = (const float*)d_in[0];
    const void*  ei      = d_in[1];
    const float* Win     = (const float*)d_in[2];
    const float* bin     = (const float*)d_in[3];
    const float* Wq      = (const float*)d_in[4];
    const float* bq      = (const float*)d_in[5];
    const float* Wk      = (const float*)d_in[6];
    const float* bk      = (const float*)d_in[7];
    const float* Wv      = (const float*)d_in[8];
    const float* bv      = (const float*)d_in[9];
    const float* hopwise = (const float*)d_in[10];
    float*       out     = (float*)d_out;

    int n  = in_sizes[0] / FIN;   // 100000
    int ne = in_sizes[1] / 2;     // 800000
    int nb8 = (n + 7) / 8;

    // one-time side stream + events (host objects only; no device allocation)
    static cudaStream_t s2 = nullptr;
    static cudaEvent_t  ev0 = nullptr, ev1 = nullptr;
    if (s2 == nullptr) {
        cudaStreamCreateWithFlags(&s2, cudaStreamNonBlocking);
        cudaEventCreateWithFlags(&ev0, cudaEventDisableTiming);
        cudaEventCreateWithFlags(&ev1, cudaEventDisableTiming);
    }

    void* degp = nullptr;
    cudaGetSymbolAddress(&degp, g_deg);

    // fork: CSR chain on s2 runs concurrently with feat on the main stream
    cudaEventRecord(ev0, 0);
    cudaStreamWaitEvent(s2, ev0, 0);
    cudaMemsetAsync(degp, 0, NN * sizeof(int), s2);
    count_kernel<<<1024, 256, 0, s2>>>(ei, ne, n);
    scan1_kernel<<<1, 1024, 0, s2>>>(n);
    scatter_kernel<<<1024, 256, 0, s2>>>(ei, ne, n);
    cudaEventRecord(ev1, s2);

    feat_kernel<<<nb8, 256>>>(feat, Win, bin, Wq, bq, Wk, bk, Wv, bv,
                              hopwise, out, n);

    // join: hops need both feat (Q, KV0) and scatter (g_off/g_adj)
    cudaStreamWaitEvent(0, ev1, 0);

    hop1_kernel<<<nb8, 256>>>(out, hopwise, n);
    hop_kernel<<<nb8, 256>>>(out, hopwise, 1, 0, 1, n);
    hop_kernel<<<nb8, 256>>>(out, hopwise, 2, 1, 0, n);
}

// round 17
// speedup vs baseline: 1.0977x; 1.0129x over previous
#include <cuda_runtime.h>
#include <cuda_fp16.h>
#include <math.h>

#define NN   100000
#define NE   800000
#define FIN  128
#define C    32
#define D    16
#define CST  1e-5f

// ---------- persistent scratch (device globals; no allocation allowed) ----------
__device__ float  g_Q[NN * C];                         // 12.8 MB
__device__ __align__(16) __half g_KV0[NN * 64];        // 12.8 MB: 32 K + 16 V + 16 pad (128B row)
__device__ __align__(16) __half g_Kh[2][NN * C];       // 2 x 6.4 MB  (K1, K2)
// M rows stored TRANSPOSED: element idx = j*32 + i  (j in [0,16), i in [0,32))
// -> warp lane l owns elements [16l, 16l+16) = 2 contiguous uint4
__device__ __align__(16) __half g_Mh[2][NN * C * D];   // 2 x 102.4 MB (row = 512 halfs)
__device__ __align__(16) int g_deg[NN];
__device__ int    g_off[NN + 1];
__device__ int    g_cur[NN];
__device__ int    g_adj[NE];

// ---------------------------------------------- inline edge dtype detection ---
__device__ __forceinline__ int edge_is64(const void* __restrict__ ei, int n) {
    const long long* p = (const long long*)ei;
    long long v = p[threadIdx.x & 15];
    return __all_sync(0xffffffffu, v >= 0 && v < (long long)n);
}

// -------------------------------------------------------------- half helpers --
__device__ __forceinline__ void cvt8(uint4 u, float* f) {
    float2 p;
    p = __half22float2(*reinterpret_cast<const __half2*>(&u.x)); f[0] = p.x; f[1] = p.y;
    p = __half22float2(*reinterpret_cast<const __half2*>(&u.y)); f[2] = p.x; f[3] = p.y;
    p = __half22float2(*reinterpret_cast<const __half2*>(&u.z)); f[4] = p.x; f[5] = p.y;
    p = __half22float2(*reinterpret_cast<const __half2*>(&u.w)); f[6] = p.x; f[7] = p.y;
}
__device__ __forceinline__ uint4 pack8(const float* f) {
    __half2 h0 = __floats2half2_rn(f[0], f[1]);
    __half2 h1 = __floats2half2_rn(f[2], f[3]);
    __half2 h2 = __floats2half2_rn(f[4], f[5]);
    __half2 h3 = __floats2half2_rn(f[6], f[7]);
    uint4 u;
    u.x = *(unsigned*)&h0; u.y = *(unsigned*)&h1;
    u.z = *(unsigned*)&h2; u.w = *(unsigned*)&h3;
    return u;
}

// ---------------------------------------------------------------- CSR chain ---
__global__ void count_kernel(const void* __restrict__ ei, int ne, int n) {
    int is64 = edge_is64(ei, n);
    const long long* p64 = (const long long*)ei;
    const int*       p32 = (const int*)ei;
    for (int e = blockIdx.x * blockDim.x + threadIdx.x; e < ne; e += gridDim.x * blockDim.x) {
        int c = is64 ? (int)p64[ne + e] : p32[ne + e];
        atomicAdd(&g_deg[c], 1);
    }
}

__global__ void scan1_kernel(int n) {
    __shared__ int wsum[32];
    __shared__ int carry;
    int tid = threadIdx.x, lane = tid & 31, w = tid >> 5;
    if (tid == 0) carry = 0;
    __syncthreads();
    for (int base = 0; base < n; base += 4096) {
        int i = base + tid * 4;
        int4 v = make_int4(0, 0, 0, 0);
        if (i + 3 < n) v = *(const int4*)&g_deg[i];
        else {
            if (i     < n) v.x = g_deg[i];
            if (i + 1 < n) v.y = g_deg[i + 1];
            if (i + 2 < n) v.z = g_deg[i + 2];
        }
        int tsum = v.x + v.y + v.z + v.w;
        int s = tsum;
#pragma unroll
        for (int o = 1; o < 32; o <<= 1) {
            int t = __shfl_up_sync(0xffffffffu, s, o);
            if (lane >= o) s += t;
        }
        if (lane == 31) wsum[w] = s;
        __syncthreads();
        if (w == 0) {
            int ws = wsum[lane];
#pragma unroll
            for (int o = 1; o < 32; o <<= 1) {
                int t = __shfl_up_sync(0xffffffffu, ws, o);
                if (lane >= o) ws += t;
            }
            wsum[lane] = ws;
        }
        __syncthreads();
        int pre   = (w ? wsum[w - 1] : 0);
        int total = wsum[31];
        int o0 = carry + pre + s - tsum;
        int o1 = o0 + v.x, o2 = o1 + v.y, o3 = o2 + v.z;
        if (i     < n) { g_off[i]     = o0; g_cur[i]     = o0; }
        if (i + 1 < n) { g_off[i + 1] = o1; g_cur[i + 1] = o1; }
        if (i + 2 < n) { g_off[i + 2] = o2; g_cur[i + 2] = o2; }
        if (i + 3 < n) { g_off[i + 3] = o3; g_cur[i + 3] = o3; }
        __syncthreads();
        if (tid == 0) carry += total;
        __syncthreads();
    }
    if (tid == 0) g_off[n] = carry;
}

__global__ void scatter_kernel(const void* __restrict__ ei, int ne, int n) {
    const long long* p64 = (const long long*)ei;
    const int*       p32 = (const int*)ei;
    int is64 = edge_is64(ei, n);
    for (int e = blockIdx.x * blockDim.x + threadIdx.x; e < ne; e += gridDim.x * blockDim.x) {
        int c = is64 ? (int)p64[ne + e] : p32[ne + e];
        int r = is64 ? (int)p64[e]      : p32[e];
        int p = atomicAdd(&g_cur[c], 1);
        g_adj[p] = r;
    }
}

// ---------------------------------------------------------- front-end (feat) --
__global__ void feat_kernel(const float* __restrict__ feat,
                            const float* __restrict__ Win, const float* __restrict__ bin,
                            const float* __restrict__ Wq,  const float* __restrict__ bq,
                            const float* __restrict__ Wk,  const float* __restrict__ bk,
                            const float* __restrict__ Wv,  const float* __restrict__ bv,
                            const float* __restrict__ hopwise,
                            float* __restrict__ out, int n) {
    __shared__ float sWin[FIN * C];
    __shared__ float sWq[C * C], sWk[C * C], sWv[C * D];
    __shared__ float sb[3 * C + D];
    __shared__ float sx [8][FIN];
    __shared__ float sxs[8][C];

    int tid = threadIdx.x;
    for (int i = tid; i < FIN * C; i += 256) sWin[i] = Win[i];
    for (int i = tid; i < C * C;   i += 256) { sWq[i] = Wq[i]; sWk[i] = Wk[i]; }
    for (int i = tid; i < C * D;   i += 256) sWv[i] = Wv[i];
    if (tid < C) { sb[tid] = bin[tid]; sb[C + tid] = bq[tid]; sb[2 * C + tid] = bk[tid]; }
    if (tid < D) sb[3 * C + tid] = bv[tid];
    __syncthreads();

    int w = tid >> 5, lane = tid & 31;
    int node = blockIdx.x * 8 + w;
    if (node >= n) return;

    ((float4*)sx[w])[lane] = ((const float4*)feat)[node * (FIN / 4) + lane];
    __syncwarp();

    float acc = sb[lane];
#pragma unroll 8
    for (int i = 0; i < FIN; i++) acc = fmaf(sx[w][i], sWin[i * C + lane], acc);
    float x = fmaxf(acc, 0.f);
    sxs[w][lane] = x;
    __syncwarp();

    float qz = sb[C + lane], kz = sb[2 * C + lane];
    float vz = (lane < D) ? sb[3 * C + lane] : 0.f;
#pragma unroll
    for (int i = 0; i < C; i++) {
        float xi = sxs[w][i];
        qz = fmaf(xi, sWq[i * C + lane], qz);
        kz = fmaf(xi, sWk[i * C + lane], kz);
        if (lane < D) vz = fmaf(xi, sWv[i * D + lane], vz);
    }
    float q = (qz > 0.f) ? 1.f + qz : expf(qz);  // 1 + elu
    float k = (kz > 0.f) ? 1.f + kz : expf(kz);

    g_Q[node * C + lane] = q;

    __half* kv = &g_KV0[(size_t)node * 64];
    kv[lane] = __float2half_rn(k);
    if (lane < D) kv[32 + lane] = __float2half_rn(vz);
    if (lane < 16) kv[48 + lane] = __half(0.f);

    if (lane < D) out[node * D + lane] = hopwise[0] * vz;
}

// ------------------------------------------------------------- hop 1 (rank-1) -
// Warp per node (R10 layout). Lane l: h = l&1 (i-half), j = l>>1 (V column).
__global__ void hop1_kernel(float* __restrict__ out,
                            const float* __restrict__ hopwise, int n) {
    int wid = threadIdx.x >> 5, lane = threadIdx.x & 31;
    int c = blockIdx.x * 8 + wid;
    if (c >= n) return;
    int h = lane & 1, j = lane >> 1;
    int start = g_off[c], end = g_off[c + 1];

    float macc[16], kacc[16];
#pragma unroll
    for (int m = 0; m < 16; m++) { macc[m] = 0.f; kacc[m] = 0.f; }

    for (int base = start; base < end; base += 32) {
        int cnt = end - base; if (cnt > 32) cnt = 32;
        int myadj = (lane < cnt) ? g_adj[base + lane] : 0;
#pragma unroll 4
        for (int e = 0; e < cnt; e++) {
            int r = __shfl_sync(0xffffffffu, myadj, e);
            const __half* kv = &g_KV0[(size_t)r * 64];
            const uint4* kv4 = (const uint4*)kv;
            uint4 ua = kv4[2 * h], ub = kv4[2 * h + 1];   // K halfs [16h,16h+16)
            float v = __half2float(kv[32 + j]);
            float kf[16];
            cvt8(ua, kf); cvt8(ub, kf + 8);
#pragma unroll
            for (int m = 0; m < 16; m++) {
                kacc[m] += kf[m];
                macc[m] = fmaf(kf[m], v, macc[m]);
            }
        }
    }

    // store M1 row (transposed layout: lane's 16 elements at 16*lane)
    {
        uint4* mr = (uint4*)&g_Mh[0][(size_t)c * 512];
        mr[2 * lane]     = pack8(macc);
        mr[2 * lane + 1] = pack8(macc + 8);
    }
    if (lane < 2) {
        uint4* kr = (uint4*)&g_Kh[0][c * 32];
        kr[2 * lane]     = pack8(kacc);
        kr[2 * lane + 1] = pack8(kacc + 8);
    }

    // epilogue: H_j = sum_i Q_i M[j][i],  C = sum_i Q_i K1_i
    float qv[16];
    {
        const float4* qp = (const float4*)&g_Q[c * 32 + 16 * h];
        float4 q0 = qp[0], q1 = qp[1], q2 = qp[2], q3 = qp[3];
        qv[0]=q0.x; qv[1]=q0.y; qv[2]=q0.z; qv[3]=q0.w;
        qv[4]=q1.x; qv[5]=q1.y; qv[6]=q1.z; qv[7]=q1.w;
        qv[8]=q2.x; qv[9]=q2.y; qv[10]=q2.z; qv[11]=q2.w;
        qv[12]=q3.x; qv[13]=q3.y; qv[14]=q3.z; qv[15]=q3.w;
    }
    float hp = 0.f, cp = 0.f;
#pragma unroll
    for (int m = 0; m < 16; m++) {
        hp = fmaf(qv[m], macc[m], hp);
        cp = fmaf(qv[m], kacc[m], cp);
    }
    float Hj = hp + __shfl_xor_sync(0xffffffffu, hp, 1);
    float Cv = cp + __shfl_xor_sync(0xffffffffu, cp, 1);
    if (h == 0) out[c * 16 + j] += hopwise[1] * Hj / (Cv + CST);
}

// ------------------------------------------------------------- hops 2 & 3 -----
// Warp per node (R10 layout); lane l gathers 2 uint4 + one K half.
__global__ void hop_kernel(float* __restrict__ out,
                           const float* __restrict__ hopwise,
                           int hop, int src, int writeM, int n) {
    int wid = threadIdx.x >> 5, lane = threadIdx.x & 31;
    int c = blockIdx.x * 8 + wid;
    if (c >= n) return;
    int h = lane & 1, j = lane >> 1;
    int start = g_off[c], end = g_off[c + 1];

    const uint4*  __restrict__ Mold = (const uint4*)g_Mh[src];
    const __half* __restrict__ Kold = g_Kh[src];

    float macc[16];
#pragma unroll
    for (int m = 0; m < 16; m++) macc[m] = 0.f;
    float kacc = 0.f;   // K[i = lane]

    for (int base = start; base < end; base += 32) {
        int cnt = end - base; if (cnt > 32) cnt = 32;
        int myadj = (lane < cnt) ? g_adj[base + lane] : 0;
#pragma unroll 4
        for (int e = 0; e < cnt; e++) {
            int r = __shfl_sync(0xffffffffu, myadj, e);
            uint4 ua = Mold[(size_t)r * 64 + 2 * lane];
            uint4 ub = Mold[(size_t)r * 64 + 2 * lane + 1];
            float f[16];
            cvt8(ua, f); cvt8(ub, f + 8);
#pragma unroll
            for (int m = 0; m < 16; m++) macc[m] += f[m];
            kacc += __half2float(Kold[r * 32 + lane]);
        }
    }

    if (writeM) {
        uint4* mr = (uint4*)&g_Mh[src ^ 1][(size_t)c * 512];
        mr[2 * lane]     = pack8(macc);
        mr[2 * lane + 1] = pack8(macc + 8);
        float kn = __shfl_down_sync(0xffffffffu, kacc, 1);
        if (!(lane & 1)) {
            __half2 kk = __floats2half2_rn(kacc, kn);
            *(unsigned*)&g_Kh[src ^ 1][c * 32 + lane] = *(unsigned*)&kk;
        }
    }

    // epilogue
    float qv[16];
    {
        const float4* qp = (const float4*)&g_Q[c * 32 + 16 * h];
        float4 q0 = qp[0], q1 = qp[1], q2 = qp[2], q3 = qp[3];
        qv[0]=q0.x; qv[1]=q0.y; qv[2]=q0.z; qv[3]=q0.w;
        qv[4]=q1.x; qv[5]=q1.y; qv[6]=q1.z; qv[7]=q1.w;
        qv[8]=q2.x; qv[9]=q2.y; qv[10]=q2.z; qv[11]=q2.w;
        qv[12]=q3.x; qv[13]=q3.y; qv[14]=q3.z; qv[15]=q3.w;
    }
    float hp = 0.f;
#pragma unroll
    for (int m = 0; m < 16; m++) hp = fmaf(qv[m], macc[m], hp);
    float Hj = hp + __shfl_xor_sync(0xffffffffu, hp, 1);

    float cp = g_Q[c * 32 + lane] * kacc;
#pragma unroll
    for (int off = 16; off >= 1; off >>= 1)
        cp += __shfl_xor_sync(0xffffffffu, cp, off);

    if (h == 0) out[c * 16 + j] += hopwise[hop + 1] * Hj / (cp + CST);
}

// ------------------------------------------------------------------ launch ----
extern "C" void kernel_launch(void* const* d_in, const int* in_sizes, int n_in,
                              void* d_out, int out_size) {
    const float* feat    = (const float*)d_in[0];
    const void*  ei      = d_in[1];
    const float* Win     = (const float*)d_in[2];
    const float* bin     = (const float*)d_in[3];
    const float* Wq      = (const float*)d_in[4];
    const float* bq      = (const float*)d_in[5];
    const float* Wk      = (const float*)d_in[6];
    const float* bk      = (const float*)d_in[7];
    const float* Wv      = (const float*)d_in[8];
    const float* bv      = (const float*)d_in[9];
    const float* hopwise = (const float*)d_in[10];
    float*       out     = (float*)d_out;

    int n  = in_sizes[0] / FIN;   // 100000
    int ne = in_sizes[1] / 2;     // 800000
    int nb8 = (n + 7) / 8;

    // one-time side stream + events (host objects only; no device allocation)
    static cudaStream_t s2 = nullptr;
    static cudaEvent_t  ev0 = nullptr, ev1 = nullptr;
    if (s2 == nullptr) {
        cudaStreamCreateWithFlags(&s2, cudaStreamNonBlocking);
        cudaEventCreateWithFlags(&ev0, cudaEventDisableTiming);
        cudaEventCreateWithFlags(&ev1, cudaEventDisableTiming);
    }

    void* degp = nullptr;
    cudaGetSymbolAddress(&degp, g_deg);

    // fork: CSR chain on s2 runs concurrently with feat on the main stream
    cudaEventRecord(ev0, 0);
    cudaStreamWaitEvent(s2, ev0, 0);
    cudaMemsetAsync(degp, 0, NN * sizeof(int), s2);
    count_kernel<<<1024, 256, 0, s2>>>(ei, ne, n);
    scan1_kernel<<<1, 1024, 0, s2>>>(n);
    scatter_kernel<<<1024, 256, 0, s2>>>(ei, ne, n);
    cudaEventRecord(ev1, s2);

    feat_kernel<<<nb8, 256>>>(feat, Win, bin, Wq, bq, Wk, bk, Wv, bv,
                              hopwise, out, n);

    // join: hops need both feat (Q, KV0) and scatter (g_off/g_adj)
    cudaStreamWaitEvent(0, ev1, 0);

    hop1_kernel<<<nb8, 256>>>(out, hopwise, n);
    hop_kernel<<<nb8, 256>>>(out, hopwise, 1, 0, 1, n);
    hop_kernel<<<nb8, 256>>>(out, hopwise, 2, 1, 0, n);
}